// round 4
// baseline (speedup 1.0000x reference)
#include <cuda_runtime.h>
#include <cstdint>

// Problem shapes (fixed)
#define Bq 8
#define Eq 8
#define Cq 1024
#define Iq 128
#define Oq 256
#define Tq 8192

#define NTHREADS 256
#define BM 64
#define BN 128

// smem layout: bias[256] at 0, A tile (64x512B = 32KB), B tile (128x512B = 64KB)
#define SMEM_BIAS 0
#define SMEM_A    1024
#define SMEM_B    (SMEM_A + BM * 512)
#define SMEM_TOTAL (SMEM_B + BN * 512)   // 1024 + 32768 + 65536 = 99328

__device__ __forceinline__ uint32_t smem_u32(const void* p) {
    uint32_t a;
    asm("{ .reg .u64 t; cvta.to.shared.u64 t, %1; cvt.u32.u64 %0, t; }"
        : "=r"(a) : "l"(p));
    return a;
}

__device__ __forceinline__ uint32_t f2tf32(float f) {
    uint32_t r;
    asm("cvt.rna.tf32.f32 %0, %1;" : "=r"(r) : "f"(f));
    return r;
}

#define LDSM_X4(r0, r1, r2, r3, addr) \
    asm volatile("ldmatrix.sync.aligned.m8n8.x4.shared.b16 {%0,%1,%2,%3}, [%4];" \
                 : "=r"(r0), "=r"(r1), "=r"(r2), "=r"(r3) : "r"(addr))

#define MMA_TF32(c, a, b0, b1) \
    asm volatile("mma.sync.aligned.m16n8k8.row.col.f32.tf32.tf32.f32 " \
                 "{%0,%1,%2,%3}, {%4,%5,%6,%7}, {%8,%9}, {%0,%1,%2,%3};" \
                 : "+f"((c)[0]), "+f"((c)[1]), "+f"((c)[2]), "+f"((c)[3]) \
                 : "r"((a)[0]), "r"((a)[1]), "r"((a)[2]), "r"((a)[3]), \
                   "r"(b0), "r"(b1))

// ---------------------------------------------------------------------------
// tf32 mma.sync GEMM + bias + gate + red.v4 scatter (permuted B columns)
// Grid: (Oq/BN=2, Cq/BM=16, 64).  Block: 256 threads (8 warps: 2m x 4n).
// Warp tile 32(m) x 32(n): 2 m16-tiles x 4 n8-tiles x 16 k8-steps.
// B tile column permutation P(s) = ((s>>3)>>1)*16 + (s&7)*2 + ((s>>3)&1)
// makes each thread's 4 accum columns (from an n8-tile pair) contiguous in
// the real output, enabling red.global.add.v4.f32.
// ---------------------------------------------------------------------------
extern "C" __global__ void __launch_bounds__(NTHREADS, 2)
moe_mma_scatter(const float* __restrict__ x,
                const int*   __restrict__ idx,
                const float* __restrict__ gate,
                const float* __restrict__ w,
                const float* __restrict__ bias,
                float* __restrict__ out) {
    extern __shared__ char smem[];
    const uint32_t sbase = smem_u32(smem);
    const int tid  = threadIdx.x;
    const int wid  = tid >> 5;
    const int lane = tid & 31;

    const int be = blockIdx.z;            // b*Eq + e
    const int b  = be >> 3;
    const int e  = be & 7;
    const int m0 = blockIdx.y * BM;       // capacity-row offset
    const int n_base = blockIdx.x * BN;   // output-feature offset

    const float* xb = x + ((long)be * Cq + m0) * Iq;
    const float* wb = w + ((long)e * Oq + n_base) * Iq;

    float* As = reinterpret_cast<float*>(smem + SMEM_A);
    float* Bs = reinterpret_cast<float*>(smem + SMEM_B);

    // --- A tile: 64 rows x 128 cols tf32, chunk-XOR swizzle ---
    #pragma unroll
    for (int t = tid; t < BM * 32; t += NTHREADS) {
        int r = t >> 5, c4 = t & 31;
        float4 v = reinterpret_cast<const float4*>(xb + r * Iq)[c4];
        uint4 p = make_uint4(f2tf32(v.x), f2tf32(v.y), f2tf32(v.z), f2tf32(v.w));
        int off = r * 128 + ((c4 ^ (r & 7)) << 2);     // in floats
        *reinterpret_cast<uint4*>(As + off) = p;
    }
    // --- B tile: 128 rows, permuted: smem row s <- weight row n_base+P(s) ---
    #pragma unroll
    for (int t = tid; t < BN * 32; t += NTHREADS) {
        int s = t >> 5, c4 = t & 31;
        int tt = s >> 3, q = s & 7;
        int pr = ((tt >> 1) << 4) + (q << 1) + (tt & 1);   // P(s)
        float4 v = reinterpret_cast<const float4*>(wb + pr * Iq)[c4];
        uint4 p = make_uint4(f2tf32(v.x), f2tf32(v.y), f2tf32(v.z), f2tf32(v.w));
        int off = s * 128 + ((c4 ^ (s & 7)) << 2);
        *reinterpret_cast<uint4*>(Bs + off) = p;
    }
    if (tid < 256) reinterpret_cast<float*>(smem + SMEM_BIAS)[tid] = bias[tid];
    __syncthreads();

    // --- Warp/lane geometry: 2m x 4n warps, warp tile 32x32 ---
    const int m_w = (wid & 1) * 32;
    const int n_w = (wid >> 1) * 32;      // smem-B row offset (permuted space)
    const int sub = lane >> 3;
    const int l7  = lane & 7;

    const int a_r[2] = { m_w + (sub & 1) * 8 + l7, m_w + 16 + (sub & 1) * 8 + l7 };
    const int a_kh = sub >> 1;
    const int b_kh = sub & 1;
    int b_n[2];
    #pragma unroll
    for (int jp = 0; jp < 2; jp++) b_n[jp] = n_w + jp * 16 + (sub >> 1) * 8 + l7;

    float acc[2][4][4];
    #pragma unroll
    for (int i = 0; i < 2; i++)
        #pragma unroll
        for (int j = 0; j < 4; j++)
            #pragma unroll
            for (int qd = 0; qd < 4; qd++) acc[i][j][qd] = 0.f;

    const uint32_t a_base = sbase + SMEM_A;
    const uint32_t b_base = sbase + SMEM_B;

    #pragma unroll
    for (int ks = 0; ks < 16; ks++) {
        const int kc = ks * 2;
        uint32_t Af[2][4];
        #pragma unroll
        for (int i = 0; i < 2; i++) {
            uint32_t chunk = (uint32_t)((kc + a_kh) ^ l7);
            LDSM_X4(Af[i][0], Af[i][1], Af[i][2], Af[i][3],
                    a_base + a_r[i] * 512 + (chunk << 4));
        }
        uint32_t Bf[2][4];
        #pragma unroll
        for (int jp = 0; jp < 2; jp++) {
            uint32_t chunk = (uint32_t)((kc + b_kh) ^ l7);
            LDSM_X4(Bf[jp][0], Bf[jp][1], Bf[jp][2], Bf[jp][3],
                    b_base + b_n[jp] * 512 + (chunk << 4));
        }
        #pragma unroll
        for (int i = 0; i < 2; i++)
            #pragma unroll
            for (int j = 0; j < 4; j++)
                MMA_TF32(acc[i][j], Af[i], Bf[j >> 1][(j & 1) * 2],
                         Bf[j >> 1][(j & 1) * 2 + 1]);
    }

    // --- Epilogue: bias + gate + red.v4 scatter ---
    // Thread owns, per (i, half), two v4 groups (n8-tile pairs jj=0,1):
    //   global col base = n_base + ((n_w>>3) + 2*jj)>>1 * 16 + (lane&3)*4
    const float* bias_s = reinterpret_cast<const float*>(smem + SMEM_BIAS);
    const float* gb = gate + (long)be * Cq + m0;
    const int*   ib = idx  + (long)be * Cq + m0;
    const int qrow  = lane >> 2;
    const int colq  = (lane & 3) * 4;

    #pragma unroll
    for (int i = 0; i < 2; i++) {
        #pragma unroll
        for (int half = 0; half < 2; half++) {
            int r = m_w + i * 16 + half * 8 + qrow;
            float g = gb[r];
            int tok = ib[r];
            float* orow = out + ((long)b * Tq + tok) * Oq;
            #pragma unroll
            for (int jj = 0; jj < 2; jj++) {
                int col = n_base + ((n_w >> 4) + jj) * 16 + colq;
                float4 bv = *reinterpret_cast<const float4*>(bias_s + col);
                float v0 = (acc[i][2 * jj + 0][half * 2 + 0] + bv.x) * g;
                float v1 = (acc[i][2 * jj + 1][half * 2 + 0] + bv.y) * g;
                float v2 = (acc[i][2 * jj + 0][half * 2 + 1] + bv.z) * g;
                float v3 = (acc[i][2 * jj + 1][half * 2 + 1] + bv.w) * g;
                asm volatile("red.global.add.v4.f32 [%0], {%1, %2, %3, %4};"
                             :: "l"(orow + col), "f"(v0), "f"(v1), "f"(v2), "f"(v3)
                             : "memory");
            }
        }
    }
}

// ---------------------------------------------------------------------------
// kernel_launch
// Inputs: x_expert f32, expert_indices i32, expert_gate f32, weight f32,
//         bias f32, num_tokens i32 (unused)
// ---------------------------------------------------------------------------
extern "C" void kernel_launch(void* const* d_in, const int* in_sizes, int n_in,
                              void* d_out, int out_size) {
    const float* x    = (const float*)d_in[0];
    const int*   idx  = (const int*)  d_in[1];
    const float* gate = (const float*)d_in[2];
    const float* w    = (const float*)d_in[3];
    const float* bias = (const float*)d_in[4];
    float* out = (float*)d_out;

    // Zero the (B, T, O) output via a memset node (graph-capturable)
    cudaMemsetAsync(out, 0, (size_t)Bq * Tq * Oq * sizeof(float), 0);

    cudaFuncSetAttribute(moe_mma_scatter,
                         cudaFuncAttributeMaxDynamicSharedMemorySize, SMEM_TOTAL);
    dim3 grid(Oq / BN, Cq / BM, Bq * Eq);   // (2, 16, 64) = 2048 CTAs
    moe_mma_scatter<<<grid, NTHREADS, SMEM_TOTAL>>>(x, idx, gate, w, bias, out);
}

// round 5
// speedup vs baseline: 1.5109x; 1.5109x over previous
#include <cuda_runtime.h>
#include <cstdint>

// Problem shapes (fixed)
#define Bq 8
#define Eq 8
#define Cq 1024
#define Iq 128
#define Oq 256
#define Tq 8192

#define NTHREADS 256
#define BM 128
#define BN 128

// smem: bias[256] at 0, A tile (128x512B = 64KB), B tile (128x512B = 64KB)
#define SMEM_BIAS 0
#define SMEM_A    1024
#define SMEM_B    (SMEM_A + BM * 512)
#define SMEM_TOTAL (SMEM_B + BN * 512)   // 132096

__device__ __forceinline__ uint32_t smem_u32(const void* p) {
    uint32_t a;
    asm("{ .reg .u64 t; cvta.to.shared.u64 t, %1; cvt.u32.u64 %0, t; }"
        : "=r"(a) : "l"(p));
    return a;
}

__device__ __forceinline__ uint32_t f2tf32(float f) {
    uint32_t r;
    asm("cvt.rna.tf32.f32 %0, %1;" : "=r"(r) : "f"(f));
    return r;
}

#define LDSM_X4(r0, r1, r2, r3, addr) \
    asm volatile("ldmatrix.sync.aligned.m8n8.x4.shared.b16 {%0,%1,%2,%3}, [%4];" \
                 : "=r"(r0), "=r"(r1), "=r"(r2), "=r"(r3) : "r"(addr))

#define MMA_TF32(c, a, b0, b1) \
    asm volatile("mma.sync.aligned.m16n8k8.row.col.f32.tf32.tf32.f32 " \
                 "{%0,%1,%2,%3}, {%4,%5,%6,%7}, {%8,%9}, {%0,%1,%2,%3};" \
                 : "+f"((c)[0]), "+f"((c)[1]), "+f"((c)[2]), "+f"((c)[3]) \
                 : "r"((a)[0]), "r"((a)[1]), "r"((a)[2]), "r"((a)[3]), \
                   "r"(b0), "r"(b1))

// ---------------------------------------------------------------------------
// Zero-init output (faster than cudaMemsetAsync: 11.2us vs 18us measured)
// ---------------------------------------------------------------------------
__global__ void zero_kernel(float* __restrict__ out, int n4) {
    float4 z = make_float4(0.f, 0.f, 0.f, 0.f);
    for (int i = blockIdx.x * blockDim.x + threadIdx.x; i < n4;
         i += gridDim.x * blockDim.x) {
        reinterpret_cast<float4*>(out)[i] = z;
    }
}

// ---------------------------------------------------------------------------
// tf32 mma.sync GEMM, K-chunk software pipeline, permuted-B red.v4 scatter.
// Grid: (2, 8, 64) = 1024 CTAs.  Block: 256 threads (8 warps: 4m x 2n).
// Warp tile 32(m) x 64(n).  K pipelined in 4 chunks of 32.
// B smem row s holds weight row P(s) = ((s>>4)<<4) + ((s&7)<<1) + ((s>>3)&1),
// making each thread's 4 accum cols per n8-tile-pair contiguous -> red.v4.
// ---------------------------------------------------------------------------
extern "C" __global__ void __launch_bounds__(NTHREADS, 1)
moe_mma_scatter(const float* __restrict__ x,
                const int*   __restrict__ idx,
                const float* __restrict__ gate,
                const float* __restrict__ w,
                const float* __restrict__ bias,
                float* __restrict__ out) {
    extern __shared__ char smem[];
    const uint32_t sbase = smem_u32(smem);
    const int tid  = threadIdx.x;
    const int wid  = tid >> 5;
    const int lane = tid & 31;

    const int be = blockIdx.z;            // b*Eq + e
    const int b  = be >> 3;
    const int e  = be & 7;
    const int m0 = blockIdx.y * BM;
    const int n_base = blockIdx.x * BN;

    const float* xb = x + ((long)be * Cq + m0) * Iq;
    const float* wb = w + ((long)e * Oq + n_base) * Iq;

    float* As = reinterpret_cast<float*>(smem + SMEM_A);
    float* Bs = reinterpret_cast<float*>(smem + SMEM_B);

    // --- Per-thread load geometry (chunk-invariant) ---
    // Each chunk = 32 k-cols = 8 float4-cols. 128 rows x 8 c4 = 1024 items;
    // thread handles rows r0+32i (i=0..3) at c4-lane c4l.
    const int r0  = tid >> 3;
    const int c4l = tid & 7;
    int prB[4];                            // permuted weight rows for B
    #pragma unroll
    for (int i = 0; i < 4; i++) {
        int s = r0 + i * 32;
        prB[i] = ((s >> 4) << 4) + ((s & 7) << 1) + ((s >> 3) & 1);   // P(s)
    }

    // --- Warp/lane geometry: 4m x 2n warps, warp tile 32x64 ---
    const int m_w = (wid >> 1) * 32;
    const int n_w = (wid & 1) * 64;
    const int sub = lane >> 3;
    const int l7  = lane & 7;

    const int a_r[2] = { m_w + (sub & 1) * 8 + l7, m_w + 16 + (sub & 1) * 8 + l7 };
    const int a_kh = sub >> 1;
    const int b_kh = sub & 1;
    int b_n[4];
    #pragma unroll
    for (int jp = 0; jp < 4; jp++) b_n[jp] = n_w + jp * 16 + (sub >> 1) * 8 + l7;

    // --- Prefetch gate/idx rows this thread will scatter (4 rows) ---
    const int qrow = lane >> 2;
    float g_r[4];
    int   tok_r[4];
    #pragma unroll
    for (int k = 0; k < 4; k++) {
        int r = m_w + k * 8 + qrow;
        g_r[k]   = gate[(long)be * Cq + m0 + r];
        tok_r[k] = idx [(long)be * Cq + m0 + r];
    }
    if (tid < 256) reinterpret_cast<float*>(smem + SMEM_BIAS)[tid] = bias[tid];

    // --- Prefetch chunk 0 into registers ---
    float4 ra[4], rb[4];
    #pragma unroll
    for (int i = 0; i < 4; i++) {
        int r = r0 + i * 32;
        ra[i] = reinterpret_cast<const float4*>(xb + r * Iq)[c4l];
        rb[i] = reinterpret_cast<const float4*>(wb + prB[i] * Iq)[c4l];
    }
    // STS chunk 0 (cvt.rna to tf32, XOR swizzle keeps data within its chunk)
    #pragma unroll
    for (int i = 0; i < 4; i++) {
        int r = r0 + i * 32;
        int c4 = c4l;                       // chunk 0
        int off = r * 128 + ((c4 ^ (r & 7)) << 2);
        *reinterpret_cast<uint4*>(As + off) =
            make_uint4(f2tf32(ra[i].x), f2tf32(ra[i].y), f2tf32(ra[i].z), f2tf32(ra[i].w));
        *reinterpret_cast<uint4*>(Bs + off) =
            make_uint4(f2tf32(rb[i].x), f2tf32(rb[i].y), f2tf32(rb[i].z), f2tf32(rb[i].w));
    }
    __syncthreads();

    float acc[2][8][4];
    #pragma unroll
    for (int i = 0; i < 2; i++)
        #pragma unroll
        for (int j = 0; j < 8; j++)
            #pragma unroll
            for (int q = 0; q < 4; q++) acc[i][j][q] = 0.f;

    const uint32_t a_base = sbase + SMEM_A;
    const uint32_t b_base = sbase + SMEM_B;

    // --- Pipelined main loop over 4 K-chunks ---
    #pragma unroll
    for (int c = 0; c < 4; c++) {
        // Issue next chunk's LDGs (latency hidden behind this chunk's MMAs)
        if (c < 3) {
            #pragma unroll
            for (int i = 0; i < 4; i++) {
                int r = r0 + i * 32;
                int gc4 = (c + 1) * 8 + c4l;
                ra[i] = reinterpret_cast<const float4*>(xb + r * Iq + gc4 * 4)[0];
                rb[i] = reinterpret_cast<const float4*>(wb + prB[i] * Iq + gc4 * 4)[0];
            }
        }
        // MMA for this chunk: 4 k8-steps
        #pragma unroll
        for (int kk = 0; kk < 4; kk++) {
            const int ks = c * 4 + kk;
            const int kc = ks * 2;
            uint32_t Af[2][4];
            #pragma unroll
            for (int i = 0; i < 2; i++) {
                uint32_t chunk = (uint32_t)((kc + a_kh) ^ l7);
                LDSM_X4(Af[i][0], Af[i][1], Af[i][2], Af[i][3],
                        a_base + a_r[i] * 512 + (chunk << 4));
            }
            uint32_t Bf[4][4];
            #pragma unroll
            for (int jp = 0; jp < 4; jp++) {
                uint32_t chunk = (uint32_t)((kc + b_kh) ^ l7);
                LDSM_X4(Bf[jp][0], Bf[jp][1], Bf[jp][2], Bf[jp][3],
                        b_base + b_n[jp] * 512 + (chunk << 4));
            }
            #pragma unroll
            for (int i = 0; i < 2; i++)
                #pragma unroll
                for (int j = 0; j < 8; j++)
                    MMA_TF32(acc[i][j], Af[i], Bf[j >> 1][(j & 1) * 2],
                             Bf[j >> 1][(j & 1) * 2 + 1]);
        }
        // STS next chunk + barrier
        if (c < 3) {
            #pragma unroll
            for (int i = 0; i < 4; i++) {
                int r = r0 + i * 32;
                int c4 = (c + 1) * 8 + c4l;
                int off = r * 128 + ((c4 ^ (r & 7)) << 2);
                *reinterpret_cast<uint4*>(As + off) =
                    make_uint4(f2tf32(ra[i].x), f2tf32(ra[i].y), f2tf32(ra[i].z), f2tf32(ra[i].w));
                *reinterpret_cast<uint4*>(Bs + off) =
                    make_uint4(f2tf32(rb[i].x), f2tf32(rb[i].y), f2tf32(rb[i].z), f2tf32(rb[i].w));
            }
            __syncthreads();
        }
    }

    // --- Epilogue: bias + gate + red.v4 scatter (permuted-B layout) ---
    const float* bias_s = reinterpret_cast<const float*>(smem + SMEM_BIAS);
    const int colq = (lane & 3) * 4;

    #pragma unroll
    for (int i = 0; i < 2; i++) {
        #pragma unroll
        for (int half = 0; half < 2; half++) {
            const int k = i * 2 + half;
            float g = g_r[k];
            float* orow = out + ((long)b * Tq + tok_r[k]) * Oq;
            #pragma unroll
            for (int jj = 0; jj < 4; jj++) {
                int col = n_base + ((n_w >> 4) + jj) * 16 + colq;
                float4 bv = *reinterpret_cast<const float4*>(bias_s + col);
                float v0 = (acc[i][2 * jj + 0][half * 2 + 0] + bv.x) * g;
                float v1 = (acc[i][2 * jj + 1][half * 2 + 0] + bv.y) * g;
                float v2 = (acc[i][2 * jj + 0][half * 2 + 1] + bv.z) * g;
                float v3 = (acc[i][2 * jj + 1][half * 2 + 1] + bv.w) * g;
                asm volatile("red.global.add.v4.f32 [%0], {%1, %2, %3, %4};"
                             :: "l"(orow + col), "f"(v0), "f"(v1), "f"(v2), "f"(v3)
                             : "memory");
            }
        }
    }
}

// ---------------------------------------------------------------------------
// kernel_launch
// Inputs: x_expert f32, expert_indices i32, expert_gate f32, weight f32,
//         bias f32, num_tokens i32 (unused)
// ---------------------------------------------------------------------------
extern "C" void kernel_launch(void* const* d_in, const int* in_sizes, int n_in,
                              void* d_out, int out_size) {
    const float* x    = (const float*)d_in[0];
    const int*   idx  = (const int*)  d_in[1];
    const float* gate = (const float*)d_in[2];
    const float* w    = (const float*)d_in[3];
    const float* bias = (const float*)d_in[4];
    float* out = (float*)d_out;

    int n4 = (Bq * Tq * Oq) / 4;
    zero_kernel<<<4096, 256>>>(out, n4);

    cudaFuncSetAttribute(moe_mma_scatter,
                         cudaFuncAttributeMaxDynamicSharedMemorySize, SMEM_TOTAL);
    dim3 grid(Oq / BN, Cq / BM, Bq * Eq);   // (2, 8, 64) = 1024 CTAs
    moe_mma_scatter<<<grid, NTHREADS, SMEM_TOTAL>>>(x, idx, gate, w, bias, out);
}

// round 6
// speedup vs baseline: 1.7214x; 1.1393x over previous
#include <cuda_runtime.h>
#include <cstdint>

// Problem shapes (fixed)
#define Bq 8
#define Eq 8
#define Cq 1024
#define Iq 128
#define Oq 256
#define Tq 8192

#define NTHREADS 512
#define BK 32
#define STAGE_A_BYTES (128 * BK * 4)          // 16384
#define STAGE_BYTES   (2 * STAGE_A_BYTES)     // 32768 (A + B)
#define SMEM_BIAS  0
#define SMEM_TILES 1024
#define SMEM_TOTAL (SMEM_TILES + 4 * STAGE_BYTES)   // 132096

__device__ __forceinline__ uint32_t smem_u32(const void* p) {
    uint32_t a;
    asm("{ .reg .u64 t; cvta.to.shared.u64 t, %1; cvt.u32.u64 %0, t; }"
        : "=r"(a) : "l"(p));
    return a;
}

#define CP_ASYNC16(saddr, gptr) \
    asm volatile("cp.async.cg.shared.global [%0], [%1], 16;" \
                 :: "r"(saddr), "l"(gptr) : "memory")

#define LDSM_X4(r0, r1, r2, r3, addr) \
    asm volatile("ldmatrix.sync.aligned.m8n8.x4.shared.b16 {%0,%1,%2,%3}, [%4];" \
                 : "=r"(r0), "=r"(r1), "=r"(r2), "=r"(r3) : "r"(addr))

#define MMA_TF32(c, a, b0, b1) \
    asm volatile("mma.sync.aligned.m16n8k8.row.col.f32.tf32.tf32.f32 " \
                 "{%0,%1,%2,%3}, {%4,%5,%6,%7}, {%8,%9}, {%0,%1,%2,%3};" \
                 : "+f"((c)[0]), "+f"((c)[1]), "+f"((c)[2]), "+f"((c)[3]) \
                 : "r"((a)[0]), "r"((a)[1]), "r"((a)[2]), "r"((a)[3]), \
                   "r"(b0), "r"(b1))

// ---------------------------------------------------------------------------
// Zero-init output (measured faster than cudaMemsetAsync: 11.2us vs 18us)
// ---------------------------------------------------------------------------
__global__ void zero_kernel(float* __restrict__ out, int n4) {
    float4 z = make_float4(0.f, 0.f, 0.f, 0.f);
    for (int i = blockIdx.x * blockDim.x + threadIdx.x; i < n4;
         i += gridDim.x * blockDim.x) {
        reinterpret_cast<float4*>(out)[i] = z;
    }
}

// ---------------------------------------------------------------------------
// tf32 mma.sync GEMM, cp.async 4-stage K loads, register-rounded raw-f32
// fragments, permuted-B red.v4 scatter.
// Grid: (2, 8, 64) = 1024 CTAs.  Block: 512 threads (16 warps: 4m x 4n).
// Warp tile 32(m) x 32(n).  K = 4 async stages of 32.
// B smem row s holds weight row P(s) = ((s>>4)<<4) + ((s&7)<<1) + ((s>>3)&1)
// so each thread's 4 accum cols per n8-tile-pair are contiguous -> red.v4.
// tf32 rounding: fragments are raw f32 bits; +0x1000 before MMA implements
// round-to-nearest at the tf32 (low-13-bit) truncation boundary.
// ---------------------------------------------------------------------------
extern "C" __global__ void __launch_bounds__(NTHREADS, 1)
moe_mma_scatter(const float* __restrict__ x,
                const int*   __restrict__ idx,
                const float* __restrict__ gate,
                const float* __restrict__ w,
                const float* __restrict__ bias,
                float* __restrict__ out) {
    extern __shared__ char smem[];
    const uint32_t sbase = smem_u32(smem);
    const int tid  = threadIdx.x;
    const int wid  = tid >> 5;
    const int lane = tid & 31;

    const int be = blockIdx.z;            // b*Eq + e
    const int b  = be >> 3;
    const int e  = be & 7;
    const int m0 = blockIdx.y * 128;
    const int n_base = blockIdx.x * 128;

    const float* xb = x + ((long)be * Cq + m0) * Iq;
    const float* wb = w + ((long)e * Oq + n_base) * Iq;

    // bias cache
    if (tid < 256) reinterpret_cast<float*>(smem + SMEM_BIAS)[tid] = bias[tid];

    // --- Issue ALL 4 K-stages via cp.async (4 commit groups, no slot reuse) ---
    // 512 threads x 2 rows x 16B cover one 128x32 f32 tile per (A|B) per stage.
    const int lrow = tid >> 3;            // 0..63
    const int c4l  = tid & 7;
    int prB[2];
    #pragma unroll
    for (int i = 0; i < 2; i++) {
        int s = lrow + i * 64;
        prB[i] = ((s >> 4) << 4) + ((s & 7) << 1) + ((s >> 3) & 1);   // P(s)
    }
    #pragma unroll
    for (int st = 0; st < 4; st++) {
        uint32_t aB = sbase + SMEM_TILES + st * STAGE_BYTES;
        uint32_t bB = aB + STAGE_A_BYTES;
        #pragma unroll
        for (int i = 0; i < 2; i++) {
            int r = lrow + i * 64;
            uint32_t soff = (uint32_t)(r * 128 + ((c4l ^ (r & 7)) << 4));
            CP_ASYNC16(aB + soff, xb + r * Iq + st * BK + c4l * 4);
            CP_ASYNC16(bB + soff, wb + prB[i] * Iq + st * BK + c4l * 4);
        }
        asm volatile("cp.async.commit_group;" ::: "memory");
    }

    // --- Warp/lane geometry: 16 warps (4m x 4n), warp tile 32x32 ---
    const int m_w = (wid & 3) * 32;
    const int n_w = (wid >> 2) * 32;      // permuted-B smem row offset
    const int sub = lane >> 3;
    const int l7  = lane & 7;
    const int a_r[2] = { m_w + (sub & 1) * 8 + l7, m_w + 16 + (sub & 1) * 8 + l7 };
    const int a_kh = sub >> 1;
    const int b_kh = sub & 1;
    const int b_n[2] = { n_w + (sub >> 1) * 8 + l7, n_w + 16 + (sub >> 1) * 8 + l7 };

    // --- Prefetch gate/idx rows this thread scatters ---
    const int qrow = lane >> 2;
    float g_r[4];
    int   tok_r[4];
    #pragma unroll
    for (int k = 0; k < 4; k++) {
        int r = m_w + k * 8 + qrow;
        g_r[k]   = gate[(long)be * Cq + m0 + r];
        tok_r[k] = idx [(long)be * Cq + m0 + r];
    }

    float acc[2][4][4];
    #pragma unroll
    for (int i = 0; i < 2; i++)
        #pragma unroll
        for (int j = 0; j < 4; j++)
            #pragma unroll
            for (int q = 0; q < 4; q++) acc[i][j][q] = 0.f;

    // --- Main loop over 4 K-stages ---
    #pragma unroll
    for (int st = 0; st < 4; st++) {
        if      (st == 0) asm volatile("cp.async.wait_group 3;" ::: "memory");
        else if (st == 1) asm volatile("cp.async.wait_group 2;" ::: "memory");
        else if (st == 2) asm volatile("cp.async.wait_group 1;" ::: "memory");
        else              asm volatile("cp.async.wait_group 0;" ::: "memory");
        __syncthreads();

        const uint32_t aB = sbase + SMEM_TILES + st * STAGE_BYTES;
        const uint32_t bB = aB + STAGE_A_BYTES;

        #pragma unroll
        for (int kk = 0; kk < 4; kk++) {
            uint32_t Af[2][4], Bf[2][4];
            #pragma unroll
            for (int i = 0; i < 2; i++) {
                uint32_t chunk = (uint32_t)((kk * 2 + a_kh) ^ l7);
                LDSM_X4(Af[i][0], Af[i][1], Af[i][2], Af[i][3],
                        aB + a_r[i] * 128 + (chunk << 4));
            }
            #pragma unroll
            for (int jp = 0; jp < 2; jp++) {
                uint32_t chunk = (uint32_t)((kk * 2 + b_kh) ^ l7);
                LDSM_X4(Bf[jp][0], Bf[jp][1], Bf[jp][2], Bf[jp][3],
                        bB + b_n[jp] * 128 + (chunk << 4));
            }
            // tf32 round-to-nearest at the truncation boundary
            #pragma unroll
            for (int i = 0; i < 2; i++)
                #pragma unroll
                for (int q = 0; q < 4; q++) {
                    Af[i][q] += 0x1000u;
                    Bf[i][q] += 0x1000u;
                }
            #pragma unroll
            for (int i = 0; i < 2; i++)
                #pragma unroll
                for (int j = 0; j < 4; j++)
                    MMA_TF32(acc[i][j], Af[i], Bf[j >> 1][(j & 1) * 2],
                             Bf[j >> 1][(j & 1) * 2 + 1]);
        }
    }

    // --- Epilogue: bias + gate + red.v4 scatter (permuted-B layout) ---
    const float* bias_s = reinterpret_cast<const float*>(smem + SMEM_BIAS);
    const int colq = (lane & 3) * 4;

    #pragma unroll
    for (int i = 0; i < 2; i++) {
        #pragma unroll
        for (int half = 0; half < 2; half++) {
            const int k = i * 2 + half;
            float g = g_r[k];
            float* orow = out + ((long)b * Tq + tok_r[k]) * Oq;
            #pragma unroll
            for (int jj = 0; jj < 2; jj++) {
                int col = n_base + ((n_w >> 4) + jj) * 16 + colq;
                float4 bv = *reinterpret_cast<const float4*>(bias_s + col);
                float v0 = (acc[i][2 * jj + 0][half * 2 + 0] + bv.x) * g;
                float v1 = (acc[i][2 * jj + 1][half * 2 + 0] + bv.y) * g;
                float v2 = (acc[i][2 * jj + 0][half * 2 + 1] + bv.z) * g;
                float v3 = (acc[i][2 * jj + 1][half * 2 + 1] + bv.w) * g;
                asm volatile("red.global.add.v4.f32 [%0], {%1, %2, %3, %4};"
                             :: "l"(orow + col), "f"(v0), "f"(v1), "f"(v2), "f"(v3)
                             : "memory");
            }
        }
    }
}

// ---------------------------------------------------------------------------
// kernel_launch
// Inputs: x_expert f32, expert_indices i32, expert_gate f32, weight f32,
//         bias f32, num_tokens i32 (unused)
// ---------------------------------------------------------------------------
extern "C" void kernel_launch(void* const* d_in, const int* in_sizes, int n_in,
                              void* d_out, int out_size) {
    const float* x    = (const float*)d_in[0];
    const int*   idx  = (const int*)  d_in[1];
    const float* gate = (const float*)d_in[2];
    const float* w    = (const float*)d_in[3];
    const float* bias = (const float*)d_in[4];
    float* out = (float*)d_out;

    int n4 = (Bq * Tq * Oq) / 4;
    zero_kernel<<<4096, 256>>>(out, n4);

    cudaFuncSetAttribute(moe_mma_scatter,
                         cudaFuncAttributeMaxDynamicSharedMemorySize, SMEM_TOTAL);
    dim3 grid(2, 8, Bq * Eq);   // (2, 8, 64) = 1024 CTAs
    moe_mma_scatter<<<grid, NTHREADS, SMEM_TOTAL>>>(x, idx, gate, w, bias, out);
}

// round 7
// speedup vs baseline: 1.7882x; 1.0388x over previous
#include <cuda_runtime.h>
#include <cstdint>

// Problem shapes (fixed)
#define Bq 8
#define Eq 8
#define Cq 1024
#define Iq 128
#define Oq 256
#define Tq 8192

#define NTHREADS 512
#define NCTAS 148
#define NTILES 1024                            // 2 n-tiles x 8 m-tiles x 64 be
#define BK 32
#define STAGE_A_BYTES (128 * BK * 4)           // 16384
#define STAGE_BYTES   (2 * STAGE_A_BYTES)      // 32768 (A + B)
#define SMEM_BIAS  16
#define SMEM_TILES 2048
#define SMEM_TOTAL (SMEM_TILES + 4 * STAGE_BYTES)   // 133120

// Monotonic arrival counter for the zero-phase barrier. Never reset: each
// kernel run adds NCTAS arrivals; generation = ticket/NCTAS. Correct across
// any number of graph replays.
__device__ unsigned int g_zero_ctr = 0;

__device__ __forceinline__ uint32_t smem_u32(const void* p) {
    uint32_t a;
    asm("{ .reg .u64 t; cvta.to.shared.u64 t, %1; cvt.u32.u64 %0, t; }"
        : "=r"(a) : "l"(p));
    return a;
}

#define CP_ASYNC16(saddr, gptr) \
    asm volatile("cp.async.cg.shared.global [%0], [%1], 16;" \
                 :: "r"(saddr), "l"(gptr) : "memory")

#define LDSM_X4(r0, r1, r2, r3, addr) \
    asm volatile("ldmatrix.sync.aligned.m8n8.x4.shared.b16 {%0,%1,%2,%3}, [%4];" \
                 : "=r"(r0), "=r"(r1), "=r"(r2), "=r"(r3) : "r"(addr))

#define MMA_TF32(c, a, b0, b1) \
    asm volatile("mma.sync.aligned.m16n8k8.row.col.f32.tf32.tf32.f32 " \
                 "{%0,%1,%2,%3}, {%4,%5,%6,%7}, {%8,%9}, {%0,%1,%2,%3};" \
                 : "+f"((c)[0]), "+f"((c)[1]), "+f"((c)[2]), "+f"((c)[3]) \
                 : "r"((a)[0]), "r"((a)[1]), "r"((a)[2]), "r"((a)[3]), \
                   "r"(b0), "r"(b1))

// ---------------------------------------------------------------------------
// Persistent fused kernel: zero + tf32 mma.sync GEMM + red.v4 scatter.
// 148 CTAs x 512 threads, 1 CTA/SM (all resident). Each CTA: issue tile-0
// cp.async stages; zero its slice of out; release-arrive on g_zero_ctr;
// then loop its tiles with a depth-4 cross-tile cp.async ring. Before the
// FIRST atomic scatter it acquire-waits for all 148 arrivals.
// Tile t: n_base=(t&1)*128, m0=((t>>1)&7)*128, be=t>>4.
// ---------------------------------------------------------------------------
extern "C" __global__ void __launch_bounds__(NTHREADS, 1)
moe_persistent(const float* __restrict__ x,
               const int*   __restrict__ idx,
               const float* __restrict__ gate,
               const float* __restrict__ w,
               const float* __restrict__ bias,
               float* __restrict__ out) {
    extern __shared__ char smem[];
    const uint32_t sbase = smem_u32(smem);
    const int tid  = threadIdx.x;
    const int wid  = tid >> 5;
    const int lane = tid & 31;
    const int cta  = blockIdx.x;

    // --- Per-thread load geometry (tile-invariant) ---
    const int lrow = tid >> 3;            // 0..63
    const int c4l  = tid & 7;
    int prB[2];
    #pragma unroll
    for (int i = 0; i < 2; i++) {
        int s = lrow + i * 64;
        prB[i] = ((s >> 4) << 4) + ((s & 7) << 1) + ((s >> 3) & 1);   // P(s)
    }

    // --- Warp/lane geometry: 16 warps (4m x 4n), warp tile 32x32 ---
    const int m_w = (wid & 3) * 32;
    const int n_w = (wid >> 2) * 32;
    const int sub = lane >> 3;
    const int l7  = lane & 7;
    const int a_r[2] = { m_w + (sub & 1) * 8 + l7, m_w + 16 + (sub & 1) * 8 + l7 };
    const int a_kh = sub >> 1;
    const int b_kh = sub & 1;
    const int b_n[2] = { n_w + (sub >> 1) * 8 + l7, n_w + 16 + (sub >> 1) * 8 + l7 };
    const int qrow = lane >> 2;
    const int colq = (lane & 3) * 4;

    // --- Issue all 4 stages of this CTA's first tile ---
    const int t0 = cta;   // first tile (cta < 148 < 1024 always valid)
    {
        const int nb = (t0 & 1) * 128, mm = ((t0 >> 1) & 7) * 128, be = t0 >> 4;
        const float* xb = x + ((long)be * Cq + mm) * Iq;
        const float* wb = w + ((long)(be & 7) * Oq + nb) * Iq;
        #pragma unroll
        for (int st = 0; st < 4; st++) {
            uint32_t aB = sbase + SMEM_TILES + st * STAGE_BYTES;
            uint32_t bB = aB + STAGE_A_BYTES;
            #pragma unroll
            for (int i = 0; i < 2; i++) {
                int r = lrow + i * 64;
                uint32_t soff = (uint32_t)(r * 128 + ((c4l ^ (r & 7)) << 4));
                CP_ASYNC16(aB + soff, xb + r * Iq + st * BK + c4l * 4);
                CP_ASYNC16(bB + soff, wb + prB[i] * Iq + st * BK + c4l * 4);
            }
            asm volatile("cp.async.commit_group;" ::: "memory");
        }
    }

    // bias cache
    if (tid < 256) reinterpret_cast<float*>(smem + SMEM_BIAS)[tid] = bias[tid];

    // --- Zero this CTA's slice of out (overlaps the cp.async loads) ---
    {
        float4* o4 = reinterpret_cast<float4*>(out);
        const int n4 = (Bq * Tq * Oq) / 4;         // 4194304
        float4 z = make_float4(0.f, 0.f, 0.f, 0.f);
        for (int i = cta * NTHREADS + tid; i < n4; i += NCTAS * NTHREADS)
            o4[i] = z;
    }
    __threadfence();
    __syncthreads();
    unsigned bar_target = 0;
    if (tid == 0) {
        unsigned tk;
        asm volatile("atom.add.release.gpu.u32 %0, [%1], %2;"
                     : "=r"(tk) : "l"(&g_zero_ctr), "r"(1u) : "memory");
        bar_target = (tk / NCTAS + 1) * NCTAS;
    }

    // --- Persistent tile loop with depth-4 cross-tile cp.async ring ---
    bool waited = false;
    for (int t = t0; t < NTILES; t += NCTAS) {
        const int n_base = (t & 1) * 128;
        const int m0     = ((t >> 1) & 7) * 128;
        const int be     = t >> 4;
        const int b      = be >> 3;

        // gate/idx for this tile's epilogue (long-latency LDG, issued early)
        float g_r[4];
        int   tok_r[4];
        #pragma unroll
        for (int k = 0; k < 4; k++) {
            int r = m_w + k * 8 + qrow;
            g_r[k]   = gate[(long)be * Cq + m0 + r];
            tok_r[k] = idx [(long)be * Cq + m0 + r];
        }

        float acc[2][4][4];
        #pragma unroll
        for (int i = 0; i < 2; i++)
            #pragma unroll
            for (int j = 0; j < 4; j++)
                #pragma unroll
                for (int q = 0; q < 4; q++) acc[i][j][q] = 0.f;

        // next tile's pointers (for ring refill)
        const int tn = t + NCTAS;
        const float* xb_n = nullptr;
        const float* wb_n = nullptr;
        if (tn < NTILES) {
            int nb2 = (tn & 1) * 128, mm2 = ((tn >> 1) & 7) * 128, be2 = tn >> 4;
            xb_n = x + ((long)be2 * Cq + mm2) * Iq;
            wb_n = w + ((long)(be2 & 7) * Oq + nb2) * Iq;
        }

        #pragma unroll
        for (int st = 0; st < 4; st++) {
            asm volatile("cp.async.wait_group 3;" ::: "memory");
            __syncthreads();

            const uint32_t aB = sbase + SMEM_TILES + st * STAGE_BYTES;
            const uint32_t bB = aB + STAGE_A_BYTES;

            #pragma unroll
            for (int kk = 0; kk < 4; kk++) {
                uint32_t Af[2][4], Bf[2][4];
                #pragma unroll
                for (int i = 0; i < 2; i++) {
                    uint32_t chunk = (uint32_t)((kk * 2 + a_kh) ^ l7);
                    LDSM_X4(Af[i][0], Af[i][1], Af[i][2], Af[i][3],
                            aB + a_r[i] * 128 + (chunk << 4));
                }
                #pragma unroll
                for (int jp = 0; jp < 2; jp++) {
                    uint32_t chunk = (uint32_t)((kk * 2 + b_kh) ^ l7);
                    LDSM_X4(Bf[jp][0], Bf[jp][1], Bf[jp][2], Bf[jp][3],
                            bB + b_n[jp] * 128 + (chunk << 4));
                }
                // tf32 round-to-nearest at the truncation boundary
                #pragma unroll
                for (int i = 0; i < 2; i++)
                    #pragma unroll
                    for (int q = 0; q < 4; q++) {
                        Af[i][q] += 0x1000u;
                        Bf[i][q] += 0x1000u;
                    }
                #pragma unroll
                for (int i = 0; i < 2; i++)
                    #pragma unroll
                    for (int j = 0; j < 4; j++)
                        MMA_TF32(acc[i][j], Af[i], Bf[j >> 1][(j & 1) * 2],
                                 Bf[j >> 1][(j & 1) * 2 + 1]);
            }
            __syncthreads();   // all warps done reading buffer st

            // refill buffer st with next tile's stage st
            if (tn < NTILES) {
                #pragma unroll
                for (int i = 0; i < 2; i++) {
                    int r = lrow + i * 64;
                    uint32_t soff = (uint32_t)(r * 128 + ((c4l ^ (r & 7)) << 4));
                    CP_ASYNC16(aB + soff, xb_n + r * Iq + st * BK + c4l * 4);
                    CP_ASYNC16(bB + soff, wb_n + prB[i] * Iq + st * BK + c4l * 4);
                }
            }
            asm volatile("cp.async.commit_group;" ::: "memory");
        }

        // Before the FIRST atomic: wait for all CTAs' zero phases
        if (!waited) {
            if (tid == 0) {
                unsigned v;
                do {
                    asm volatile("ld.acquire.gpu.u32 %0, [%1];"
                                 : "=r"(v) : "l"(&g_zero_ctr) : "memory");
                } while (v < bar_target);
            }
            __syncthreads();
            waited = true;
        }

        // --- Epilogue: bias + gate + red.v4 scatter (permuted-B layout) ---
        const float* bias_s = reinterpret_cast<const float*>(smem + SMEM_BIAS);
        #pragma unroll
        for (int i = 0; i < 2; i++) {
            #pragma unroll
            for (int half = 0; half < 2; half++) {
                const int k = i * 2 + half;
                float g = g_r[k];
                float* orow = out + ((long)b * Tq + tok_r[k]) * Oq;
                #pragma unroll
                for (int jj = 0; jj < 2; jj++) {
                    int col = n_base + ((n_w >> 4) + jj) * 16 + colq;
                    float4 bv = *reinterpret_cast<const float4*>(bias_s + col);
                    float v0 = (acc[i][2 * jj + 0][half * 2 + 0] + bv.x) * g;
                    float v1 = (acc[i][2 * jj + 1][half * 2 + 0] + bv.y) * g;
                    float v2 = (acc[i][2 * jj + 0][half * 2 + 1] + bv.z) * g;
                    float v3 = (acc[i][2 * jj + 1][half * 2 + 1] + bv.w) * g;
                    asm volatile("red.global.add.v4.f32 [%0], {%1, %2, %3, %4};"
                                 :: "l"(orow + col), "f"(v0), "f"(v1), "f"(v2), "f"(v3)
                                 : "memory");
                }
            }
        }
    }
}

// ---------------------------------------------------------------------------
// kernel_launch
// Inputs: x_expert f32, expert_indices i32, expert_gate f32, weight f32,
//         bias f32, num_tokens i32 (unused)
// ---------------------------------------------------------------------------
extern "C" void kernel_launch(void* const* d_in, const int* in_sizes, int n_in,
                              void* d_out, int out_size) {
    const float* x    = (const float*)d_in[0];
    const int*   idx  = (const int*)  d_in[1];
    const float* gate = (const float*)d_in[2];
    const float* w    = (const float*)d_in[3];
    const float* bias = (const float*)d_in[4];
    float* out = (float*)d_out;

    cudaFuncSetAttribute(moe_persistent,
                         cudaFuncAttributeMaxDynamicSharedMemorySize, SMEM_TOTAL);
    moe_persistent<<<NCTAS, NTHREADS, SMEM_TOTAL>>>(x, idx, gate, w, bias, out);
}

// round 8
// speedup vs baseline: 1.8711x; 1.0464x over previous
#include <cuda_runtime.h>
#include <cstdint>

// Problem shapes (fixed)
#define Bq 8
#define Eq 8
#define Cq 1024
#define Iq 128
#define Oq 256
#define Tq 8192

#define NTHREADS 512
#define NCTAS 148
#define NTILES 512                    // 8 m-tiles x 64 be;  tile = 128 x 256
#define BK 32
#define STAGE_A (128 * BK * 4)        // 16384
#define STAGE_B (256 * BK * 4)        // 32768
#define STAGE_BYTES (STAGE_A + STAGE_B)            // 49152
#define SMEM_BIAS  0
#define SMEM_TILES 1024
#define SMEM_TOTAL (SMEM_TILES + 4 * STAGE_BYTES)  // 197632

// Monotonic arrival counter (never reset; generation = ticket/NCTAS).
__device__ unsigned int g_zero_ctr = 0;

__device__ __forceinline__ uint32_t smem_u32(const void* p) {
    uint32_t a;
    asm("{ .reg .u64 t; cvta.to.shared.u64 t, %1; cvt.u32.u64 %0, t; }"
        : "=r"(a) : "l"(p));
    return a;
}

#define CP_ASYNC16(saddr, gptr) \
    asm volatile("cp.async.cg.shared.global [%0], [%1], 16;" \
                 :: "r"(saddr), "l"(gptr) : "memory")

#define LDSM_X4(r0, r1, r2, r3, addr) \
    asm volatile("ldmatrix.sync.aligned.m8n8.x4.shared.b16 {%0,%1,%2,%3}, [%4];" \
                 : "=r"(r0), "=r"(r1), "=r"(r2), "=r"(r3) : "r"(addr))

#define MMA_TF32(c, a, b0, b1) \
    asm volatile("mma.sync.aligned.m16n8k8.row.col.f32.tf32.tf32.f32 " \
                 "{%0,%1,%2,%3}, {%4,%5,%6,%7}, {%8,%9}, {%0,%1,%2,%3};" \
                 : "+f"((c)[0]), "+f"((c)[1]), "+f"((c)[2]), "+f"((c)[3]) \
                 : "r"((a)[0]), "r"((a)[1]), "r"((a)[2]), "r"((a)[3]), \
                   "r"(b0), "r"(b1))

// ---------------------------------------------------------------------------
// Persistent fused kernel. 148 CTAs x 512 threads (16 warps: 4m x 4n),
// tile 128(m) x 256(n), warp tile 32x64, 4-stage single-sync cp.async ring.
// Zero stores issued early (no fence); fence+barrier deferred to just before
// the first atomic scatter so the 64MB drain overlaps tile-0 compute.
// B smem row s holds weight row P(s) = ((s>>4)<<4)+((s&7)<<1)+((s>>3)&1)
// -> per-thread contiguous 4-col groups -> red.global.add.v4.f32.
// tf32 round-to-nearest: +0x1000 on raw f32 fragments before MMA.
// ---------------------------------------------------------------------------
extern "C" __global__ void __launch_bounds__(NTHREADS, 1)
moe_persistent(const float* __restrict__ x,
               const int*   __restrict__ idx,
               const float* __restrict__ gate,
               const float* __restrict__ w,
               const float* __restrict__ bias,
               float* __restrict__ out) {
    extern __shared__ char smem[];
    const uint32_t sbase = smem_u32(smem);
    const int tid  = threadIdx.x;
    const int wid  = tid >> 5;
    const int lane = tid & 31;
    const int cta  = blockIdx.x;

    // --- Per-thread load geometry (tile-invariant) ---
    // A: rows rA, rA+64 at c4 lane c4l.  B: rows rA+{0,64,128,192} permuted.
    const int rA  = tid >> 3;             // 0..63
    const int c4l = tid & 7;
    const uint32_t soff0 = (uint32_t)(rA * 128 + ((c4l ^ (rA & 7)) << 4));
    int prB[4];
    #pragma unroll
    for (int i = 0; i < 4; i++) {
        int s = rA + i * 64;
        prB[i] = ((s >> 4) << 4) + ((s & 7) << 1) + ((s >> 3) & 1);   // P(s)
    }

    // --- Warp/lane geometry: 16 warps (4m x 4n), warp tile 32x64 ---
    const int m_w = (wid & 3) * 32;
    const int n_w = (wid >> 2) * 64;
    const int sub = lane >> 3;
    const int l7  = lane & 7;
    const int a_r[2] = { m_w + (sub & 1) * 8 + l7, m_w + 16 + (sub & 1) * 8 + l7 };
    const int a_kh = sub >> 1;
    const int b_kh = sub & 1;
    int b_n[4];
    #pragma unroll
    for (int jp = 0; jp < 4; jp++) b_n[jp] = n_w + jp * 16 + (sub >> 1) * 8 + l7;
    const int qrow = lane >> 2;
    const int colq = (lane & 3) * 4;

    // --- Prologue: issue stages 0..2 of first tile ---
    const int t0 = cta;
    const float* xb = x + ((long)(t0 >> 3) * Cq + (t0 & 7) * 128) * Iq;
    const float* wb = w + (long)((t0 >> 3) & 7) * Oq * Iq;
    #pragma unroll
    for (int st = 0; st < 3; st++) {
        uint32_t aB = sbase + SMEM_TILES + st * STAGE_BYTES;
        uint32_t bB = aB + STAGE_A;
        CP_ASYNC16(aB + soff0,                 xb + rA * Iq + st * BK + c4l * 4);
        CP_ASYNC16(aB + soff0 + 64 * 128,      xb + (rA + 64) * Iq + st * BK + c4l * 4);
        #pragma unroll
        for (int i = 0; i < 4; i++)
            CP_ASYNC16(bB + soff0 + i * 64 * 128,
                       wb + prB[i] * Iq + st * BK + c4l * 4);
        asm volatile("cp.async.commit_group;" ::: "memory");
    }

    // bias cache
    if (tid < 256) reinterpret_cast<float*>(smem + SMEM_BIAS)[tid] = bias[tid];

    // --- Issue zero stores (fire-and-forget; fence deferred) ---
    {
        float4* o4 = reinterpret_cast<float4*>(out);
        const int n4 = (Bq * Tq * Oq) / 4;
        float4 z = make_float4(0.f, 0.f, 0.f, 0.f);
        for (int i = cta * NTHREADS + tid; i < n4; i += NCTAS * NTHREADS)
            o4[i] = z;
    }

    // --- Persistent tile loop ---
    bool waited = false;
    unsigned bar_target = 0;
    for (int t = t0; t < NTILES; t += NCTAS) {
        const int m0 = (t & 7) * 128;
        const int be = t >> 3;
        const int b  = be >> 3;
        xb = x + ((long)be * Cq + m0) * Iq;
        wb = w + (long)(be & 7) * Oq * Iq;

        const int tn = t + NCTAS;
        const float* xb_n = xb;
        const float* wb_n = wb;
        if (tn < NTILES) {
            xb_n = x + ((long)(tn >> 3) * Cq + (tn & 7) * 128) * Iq;
            wb_n = w + (long)((tn >> 3) & 7) * Oq * Iq;
        }

        // gate/idx for epilogue (issued early)
        float g_r[4];
        int   tok_r[4];
        #pragma unroll
        for (int k = 0; k < 4; k++) {
            int r = m_w + k * 8 + qrow;
            g_r[k]   = gate[(long)be * Cq + m0 + r];
            tok_r[k] = idx [(long)be * Cq + m0 + r];
        }

        float acc[2][8][4];
        #pragma unroll
        for (int i = 0; i < 2; i++)
            #pragma unroll
            for (int j = 0; j < 8; j++)
                #pragma unroll
                for (int q = 0; q < 4; q++) acc[i][j][q] = 0.f;

        #pragma unroll
        for (int st = 0; st < 4; st++) {
            asm volatile("cp.async.wait_group 2;" ::: "memory");
            __syncthreads();

            // Refill buffer (st+3)&3 = previous stage's buffer (safe after sync).
            // st==0: current tile stage 3. st>=1: next tile stage st-1
            // (or reload current tile's consumed stage on the tail, keeping
            //  every commit group non-empty so wait_group counting stays valid).
            {
                const int rst = (st + 3) & 3;
                const float* rx = (st == 0) ? xb : (tn < NTILES ? xb_n : xb);
                const float* rw = (st == 0) ? wb : (tn < NTILES ? wb_n : wb);
                uint32_t aB = sbase + SMEM_TILES + rst * STAGE_BYTES;
                uint32_t bB = aB + STAGE_A;
                CP_ASYNC16(aB + soff0,            rx + rA * Iq + rst * BK + c4l * 4);
                CP_ASYNC16(aB + soff0 + 64 * 128, rx + (rA + 64) * Iq + rst * BK + c4l * 4);
                #pragma unroll
                for (int i = 0; i < 4; i++)
                    CP_ASYNC16(bB + soff0 + i * 64 * 128,
                               rw + prB[i] * Iq + rst * BK + c4l * 4);
                asm volatile("cp.async.commit_group;" ::: "memory");
            }

            // Compute stage st
            const uint32_t aB = sbase + SMEM_TILES + st * STAGE_BYTES;
            const uint32_t bB = aB + STAGE_A;
            #pragma unroll
            for (int kk = 0; kk < 4; kk++) {
                uint32_t Af[2][4], Bf[4][4];
                #pragma unroll
                for (int i = 0; i < 2; i++) {
                    uint32_t chunk = (uint32_t)((kk * 2 + a_kh) ^ l7);
                    LDSM_X4(Af[i][0], Af[i][1], Af[i][2], Af[i][3],
                            aB + a_r[i] * 128 + (chunk << 4));
                }
                #pragma unroll
                for (int jp = 0; jp < 4; jp++) {
                    uint32_t chunk = (uint32_t)((kk * 2 + b_kh) ^ l7);
                    LDSM_X4(Bf[jp][0], Bf[jp][1], Bf[jp][2], Bf[jp][3],
                            bB + b_n[jp] * 128 + (chunk << 4));
                }
                // tf32 round-to-nearest at the truncation boundary
                #pragma unroll
                for (int i = 0; i < 2; i++)
                    #pragma unroll
                    for (int q = 0; q < 4; q++) Af[i][q] += 0x1000u;
                #pragma unroll
                for (int jp = 0; jp < 4; jp++)
                    #pragma unroll
                    for (int q = 0; q < 4; q++) Bf[jp][q] += 0x1000u;
                #pragma unroll
                for (int i = 0; i < 2; i++)
                    #pragma unroll
                    for (int j = 0; j < 8; j++)
                        MMA_TF32(acc[i][j], Af[i], Bf[j >> 1][(j & 1) * 2],
                                 Bf[j >> 1][(j & 1) * 2 + 1]);
            }
        }

        // Before the FIRST scatter: fence own zero stores, arrive, wait all.
        if (!waited) {
            __threadfence();
            __syncthreads();
            if (tid == 0) {
                unsigned tk;
                asm volatile("atom.add.release.gpu.u32 %0, [%1], %2;"
                             : "=r"(tk) : "l"(&g_zero_ctr), "r"(1u) : "memory");
                bar_target = (tk / NCTAS + 1) * NCTAS;
                unsigned v;
                do {
                    asm volatile("ld.acquire.gpu.u32 %0, [%1];"
                                 : "=r"(v) : "l"(&g_zero_ctr) : "memory");
                } while (v < bar_target);
            }
            __syncthreads();
            waited = true;
        }

        // --- Epilogue: bias + gate + red.v4 scatter (permuted-B layout) ---
        const float* bias_s = reinterpret_cast<const float*>(smem + SMEM_BIAS);
        #pragma unroll
        for (int i = 0; i < 2; i++) {
            #pragma unroll
            for (int half = 0; half < 2; half++) {
                const int k = i * 2 + half;
                float g = g_r[k];
                float* orow = out + ((long)b * Tq + tok_r[k]) * Oq;
                #pragma unroll
                for (int jj = 0; jj < 4; jj++) {
                    int col = ((n_w >> 4) + jj) * 16 + colq;
                    float4 bv = *reinterpret_cast<const float4*>(bias_s + col);
                    float v0 = (acc[i][2 * jj + 0][half * 2 + 0] + bv.x) * g;
                    float v1 = (acc[i][2 * jj + 1][half * 2 + 0] + bv.y) * g;
                    float v2 = (acc[i][2 * jj + 0][half * 2 + 1] + bv.z) * g;
                    float v3 = (acc[i][2 * jj + 1][half * 2 + 1] + bv.w) * g;
                    asm volatile("red.global.add.v4.f32 [%0], {%1, %2, %3, %4};"
                                 :: "l"(orow + col), "f"(v0), "f"(v1), "f"(v2), "f"(v3)
                                 : "memory");
                }
            }
        }
    }
}

// ---------------------------------------------------------------------------
// kernel_launch
// Inputs: x_expert f32, expert_indices i32, expert_gate f32, weight f32,
//         bias f32, num_tokens i32 (unused)
// ---------------------------------------------------------------------------
extern "C" void kernel_launch(void* const* d_in, const int* in_sizes, int n_in,
                              void* d_out, int out_size) {
    const float* x    = (const float*)d_in[0];
    const int*   idx  = (const int*)  d_in[1];
    const float* gate = (const float*)d_in[2];
    const float* w    = (const float*)d_in[3];
    const float* bias = (const float*)d_in[4];
    float* out = (float*)d_out;

    cudaFuncSetAttribute(moe_persistent,
                         cudaFuncAttributeMaxDynamicSharedMemorySize, SMEM_TOTAL);
    moe_persistent<<<NCTAS, NTHREADS, SMEM_TOTAL>>>(x, idx, gate, w, bias, out);
}

// round 9
// speedup vs baseline: 1.9425x; 1.0381x over previous
#include <cuda_runtime.h>
#include <cstdint>

// Problem shapes (fixed)
#define Bq 8
#define Eq 8
#define Cq 1024
#define Iq 128
#define Oq 256
#define Tq 8192

#define NTHREADS 256
#define NCTAS 296                      // 2 persistent CTAs per SM
#define NTILES 1024                    // 2 n x 8 m x 64 be;  tile = 128 x 128
#define BK 32
#define NSTAGE 3
#define STAGE_A (128 * BK * 4)         // 16384
#define STAGE_BYTES (2 * STAGE_A)      // 32768 (A + B)
#define SMEM_BIAS  0
#define SMEM_TILES 1024
#define SMEM_TOTAL (SMEM_TILES + NSTAGE * STAGE_BYTES)   // 99328 -> 2 CTAs/SM

// Monotonic arrival counter (never reset; generation = ticket/NCTAS).
__device__ unsigned int g_zero_ctr = 0;

__device__ __forceinline__ uint32_t smem_u32(const void* p) {
    uint32_t a;
    asm("{ .reg .u64 t; cvta.to.shared.u64 t, %1; cvt.u32.u64 %0, t; }"
        : "=r"(a) : "l"(p));
    return a;
}

#define CP_ASYNC16(saddr, gptr) \
    asm volatile("cp.async.cg.shared.global [%0], [%1], 16;" \
                 :: "r"(saddr), "l"(gptr) : "memory")

#define LDSM_X4(r0, r1, r2, r3, addr) \
    asm volatile("ldmatrix.sync.aligned.m8n8.x4.shared.b16 {%0,%1,%2,%3}, [%4];" \
                 : "=r"(r0), "=r"(r1), "=r"(r2), "=r"(r3) : "r"(addr))

#define MMA_TF32(c, a, b0, b1) \
    asm volatile("mma.sync.aligned.m16n8k8.row.col.f32.tf32.tf32.f32 " \
                 "{%0,%1,%2,%3}, {%4,%5,%6,%7}, {%8,%9}, {%0,%1,%2,%3};" \
                 : "+f"((c)[0]), "+f"((c)[1]), "+f"((c)[2]), "+f"((c)[3]) \
                 : "r"((a)[0]), "r"((a)[1]), "r"((a)[2]), "r"((a)[3]), \
                   "r"(b0), "r"(b1))

// ---------------------------------------------------------------------------
// Persistent fused kernel, 2 CTAs/SM.
// 296 CTAs x 256 threads (8 warps: 4m x 2n, warp tile 32x64), tile 128x128.
// 3-buffer cp.async ring, fetch-ahead 2, ONE __syncthreads per stage:
//   stage g: wait_group 1; sync; refill chunk g+2 -> buf (g+2)%3; compute g.
// Zero stores issued early (no fence); fence + monotonic barrier deferred to
// just before the first atomic scatter.
// B smem row s holds weight row P(s)=((s>>4)<<4)+((s&7)<<1)+((s>>3)&1)
// -> contiguous per-thread 4-col groups -> red.global.add.v4.f32.
// tf32 round-to-nearest: +0x1000 on raw f32 fragments before MMA.
// Tile t: n_base=(t&1)*128, m0=((t>>1)&7)*128, be=t>>4.
// ---------------------------------------------------------------------------
extern "C" __global__ void __launch_bounds__(NTHREADS, 2)
moe_persistent(const float* __restrict__ x,
               const int*   __restrict__ idx,
               const float* __restrict__ gate,
               const float* __restrict__ w,
               const float* __restrict__ bias,
               float* __restrict__ out) {
    extern __shared__ char smem[];
    const uint32_t sbase = smem_u32(smem);
    const int tid  = threadIdx.x;
    const int wid  = tid >> 5;
    const int lane = tid & 31;
    const int cta  = blockIdx.x;

    // --- Per-thread cp.async geometry (tile-invariant) ---
    // 256 threads; per stage each half-tile (128 rows x 8 c4) = 1024 float4,
    // thread covers rows rt+32i (i<4) at c4 lane c4l.  Swizzle const per i.
    const int rt  = tid >> 3;             // 0..31
    const int c4l = tid & 7;
    const uint32_t swz = (uint32_t)((c4l ^ (rt & 7)) << 4);
    int prB[4];
    #pragma unroll
    for (int i = 0; i < 4; i++) {
        int s = rt + i * 32;
        prB[i] = ((s >> 4) << 4) + ((s & 7) << 1) + ((s >> 3) & 1);   // P(s)
    }

    // --- Warp/lane geometry: 8 warps (4m x 2n), warp tile 32x64 ---
    const int m_w = (wid >> 1) * 32;
    const int n_w = (wid & 1) * 64;
    const int sub = lane >> 3;
    const int l7  = lane & 7;
    const int a_r[2] = { m_w + (sub & 1) * 8 + l7, m_w + 16 + (sub & 1) * 8 + l7 };
    const int a_kh = sub >> 1;
    const int b_kh = sub & 1;
    int b_n[4];
    #pragma unroll
    for (int jp = 0; jp < 4; jp++) b_n[jp] = n_w + jp * 16 + (sub >> 1) * 8 + l7;
    const int qrow = lane >> 2;
    const int colq = (lane & 3) * 4;

    // --- Prologue: issue chunks 0,1 of first tile into buffers 0,1 ---
    const int t0 = cta;
    const float* xb = x + ((long)(t0 >> 4) * Cq + ((t0 >> 1) & 7) * 128) * Iq;
    const float* wb = w + (long)((t0 >> 4) & 7) * Oq * Iq + (long)(t0 & 1) * 128 * Iq;
    #pragma unroll
    for (int st = 0; st < 2; st++) {
        uint32_t aB = sbase + SMEM_TILES + st * STAGE_BYTES;
        uint32_t bB = aB + STAGE_A;
        #pragma unroll
        for (int i = 0; i < 4; i++) {
            int r = rt + i * 32;
            uint32_t soff = (uint32_t)(r * 128) + swz;
            CP_ASYNC16(aB + soff, xb + r * Iq + st * BK + c4l * 4);
            CP_ASYNC16(bB + soff, wb + prB[i] * Iq + st * BK + c4l * 4);
        }
        asm volatile("cp.async.commit_group;" ::: "memory");
    }

    // bias cache
    if (tid < 256) reinterpret_cast<float*>(smem + SMEM_BIAS)[tid] = bias[tid];

    // --- Issue zero stores (fire-and-forget; fence deferred) ---
    {
        float4* o4 = reinterpret_cast<float4*>(out);
        const int n4 = (Bq * Tq * Oq) / 4;
        float4 z = make_float4(0.f, 0.f, 0.f, 0.f);
        for (int i = cta * NTHREADS + tid; i < n4; i += NCTAS * NTHREADS)
            o4[i] = z;
    }

    // --- Persistent tile loop ---
    bool waited = false;
    int buf = 0;                         // ring buffer of next compute stage
    for (int t = t0; t < NTILES; t += NCTAS) {
        const int n_base = (t & 1) * 128;
        const int m0     = ((t >> 1) & 7) * 128;
        const int be     = t >> 4;
        const int b      = be >> 3;
        xb = x + ((long)be * Cq + m0) * Iq;
        wb = w + (long)(be & 7) * Oq * Iq + (long)n_base * Iq;

        const int tn = t + NCTAS;
        const float* xb_n = xb;
        const float* wb_n = wb;
        if (tn < NTILES) {
            xb_n = x + ((long)(tn >> 4) * Cq + ((tn >> 1) & 7) * 128) * Iq;
            wb_n = w + (long)((tn >> 4) & 7) * Oq * Iq + (long)(tn & 1) * 128 * Iq;
        }

        // gate/idx for epilogue (issued early)
        float g_r[4];
        int   tok_r[4];
        #pragma unroll
        for (int k = 0; k < 4; k++) {
            int r = m_w + k * 8 + qrow;
            g_r[k]   = gate[(long)be * Cq + m0 + r];
            tok_r[k] = idx [(long)be * Cq + m0 + r];
        }

        float acc[2][8][4];
        #pragma unroll
        for (int i = 0; i < 2; i++)
            #pragma unroll
            for (int j = 0; j < 8; j++)
                #pragma unroll
                for (int q = 0; q < 4; q++) acc[i][j][q] = 0.f;

        #pragma unroll
        for (int ks = 0; ks < 4; ks++) {
            asm volatile("cp.async.wait_group 1;" ::: "memory");
            __syncthreads();

            // Refill chunk ks+2 into buffer (buf+2)%3 (freed last stage).
            {
                const int fk = ks + 2;
                const float* rx = (fk < 4) ? xb : xb_n;
                const float* rw = (fk < 4) ? wb : wb_n;
                const int rks = fk & 3;
                int rbuf = buf + 2; if (rbuf >= NSTAGE) rbuf -= NSTAGE;
                uint32_t aB = sbase + SMEM_TILES + rbuf * STAGE_BYTES;
                uint32_t bB = aB + STAGE_A;
                #pragma unroll
                for (int i = 0; i < 4; i++) {
                    int r = rt + i * 32;
                    uint32_t soff = (uint32_t)(r * 128) + swz;
                    CP_ASYNC16(aB + soff, rx + r * Iq + rks * BK + c4l * 4);
                    CP_ASYNC16(bB + soff, rw + prB[i] * Iq + rks * BK + c4l * 4);
                }
                asm volatile("cp.async.commit_group;" ::: "memory");
            }

            // Compute chunk ks from buffer buf
            const uint32_t aB = sbase + SMEM_TILES + buf * STAGE_BYTES;
            const uint32_t bB = aB + STAGE_A;
            #pragma unroll
            for (int kk = 0; kk < 4; kk++) {
                uint32_t Af[2][4], Bf[4][4];
                #pragma unroll
                for (int i = 0; i < 2; i++) {
                    uint32_t chunk = (uint32_t)((kk * 2 + a_kh) ^ l7);
                    LDSM_X4(Af[i][0], Af[i][1], Af[i][2], Af[i][3],
                            aB + a_r[i] * 128 + (chunk << 4));
                }
                #pragma unroll
                for (int jp = 0; jp < 4; jp++) {
                    uint32_t chunk = (uint32_t)((kk * 2 + b_kh) ^ l7);
                    LDSM_X4(Bf[jp][0], Bf[jp][1], Bf[jp][2], Bf[jp][3],
                            bB + b_n[jp] * 128 + (chunk << 4));
                }
                // tf32 round-to-nearest at the truncation boundary
                #pragma unroll
                for (int i = 0; i < 2; i++)
                    #pragma unroll
                    for (int q = 0; q < 4; q++) Af[i][q] += 0x1000u;
                #pragma unroll
                for (int jp = 0; jp < 4; jp++)
                    #pragma unroll
                    for (int q = 0; q < 4; q++) Bf[jp][q] += 0x1000u;
                #pragma unroll
                for (int i = 0; i < 2; i++)
                    #pragma unroll
                    for (int j = 0; j < 8; j++)
                        MMA_TF32(acc[i][j], Af[i], Bf[j >> 1][(j & 1) * 2],
                                 Bf[j >> 1][(j & 1) * 2 + 1]);
            }
            buf = buf + 1; if (buf >= NSTAGE) buf = 0;
        }

        // Before the FIRST scatter: fence own zero stores, arrive, wait all.
        if (!waited) {
            __threadfence();
            __syncthreads();
            if (tid == 0) {
                unsigned tk;
                asm volatile("atom.add.release.gpu.u32 %0, [%1], %2;"
                             : "=r"(tk) : "l"(&g_zero_ctr), "r"(1u) : "memory");
                unsigned bar_target = (tk / NCTAS + 1) * NCTAS;
                unsigned v;
                do {
                    asm volatile("ld.acquire.gpu.u32 %0, [%1];"
                                 : "=r"(v) : "l"(&g_zero_ctr) : "memory");
                } while (v < bar_target);
            }
            __syncthreads();
            waited = true;
        }

        // --- Epilogue: bias + gate + red.v4 scatter (permuted-B layout) ---
        const float* bias_s = reinterpret_cast<const float*>(smem + SMEM_BIAS);
        #pragma unroll
        for (int i = 0; i < 2; i++) {
            #pragma unroll
            for (int half = 0; half < 2; half++) {
                const int k = i * 2 + half;
                float g = g_r[k];
                float* orow = out + ((long)b * Tq + tok_r[k]) * Oq;
                #pragma unroll
                for (int jj = 0; jj < 4; jj++) {
                    int col = n_base + ((n_w >> 4) + jj) * 16 + colq;
                    float4 bv = *reinterpret_cast<const float4*>(bias_s + col);
                    float v0 = (acc[i][2 * jj + 0][half * 2 + 0] + bv.x) * g;
                    float v1 = (acc[i][2 * jj + 1][half * 2 + 0] + bv.y) * g;
                    float v2 = (acc[i][2 * jj + 0][half * 2 + 1] + bv.z) * g;
                    float v3 = (acc[i][2 * jj + 1][half * 2 + 1] + bv.w) * g;
                    asm volatile("red.global.add.v4.f32 [%0], {%1, %2, %3, %4};"
                                 :: "l"(orow + col), "f"(v0), "f"(v1), "f"(v2), "f"(v3)
                                 : "memory");
                }
            }
        }
    }
}

// ---------------------------------------------------------------------------
// kernel_launch
// Inputs: x_expert f32, expert_indices i32, expert_gate f32, weight f32,
//         bias f32, num_tokens i32 (unused)
// ---------------------------------------------------------------------------
extern "C" void kernel_launch(void* const* d_in, const int* in_sizes, int n_in,
                              void* d_out, int out_size) {
    const float* x    = (const float*)d_in[0];
    const int*   idx  = (const int*)  d_in[1];
    const float* gate = (const float*)d_in[2];
    const float* w    = (const float*)d_in[3];
    const float* bias = (const float*)d_in[4];
    float* out = (float*)d_out;

    cudaFuncSetAttribute(moe_persistent,
                         cudaFuncAttributeMaxDynamicSharedMemorySize, SMEM_TOTAL);
    moe_persistent<<<NCTAS, NTHREADS, SMEM_TOTAL>>>(x, idx, gate, w, bias, out);
}